// round 3
// baseline (speedup 1.0000x reference)
#include <cuda_runtime.h>
#include <math.h>

// ---------------------------------------------------------------------------
// Wavelet scattering, T=16384, B=16, n1=64, n2=8, P=224, output stride 256.
//
// Design:
//  * All length-16384 FFTs are done in-place in shared memory (128KB/CTA),
//    radix-4, 7 stages, 1024 threads (4 butterflies/thread/stage).
//  * Forward = DIF (natural -> base-4 digit-reversed). Inverse = DIT
//    (digit-reversed -> natural), exact algebraic inverse of the DIF stages
//    (unnormalized; the 1/N is folded into the permuted psi filters).
//  * Filters psi1/psi2 are pre-permuted into digit-reversed order once per
//    call by an init kernel, so pointwise products need no reordering.
//  * Lowpass + downsample-by-256 is done as a time-domain circular
//    convolution with phi_time (truncated Gaussian, +/-768 taps, computed
//    exactly from phi_hat via the twiddle table). This removes the need for
//    any FFT of U2 (3584 FFTs saved) and the final folded IDFTs.
// ---------------------------------------------------------------------------

#define T_N    16384
#define B_N    16
#define N1     64
#define N2     8
#define P_N    224
#define M_OUT  64
#define W_PHI  768
#define SMEM_BYTES (T_N * (int)sizeof(float2))

// Output layout (tuple flattened + concatenated):
//  S0: [B,1,64]   at offset 0                (1024 floats)
//  S1: [B,64,64]  at offset 1024             (65536 floats)
//  S2: [B,224,64] at offset 66560            (229376 floats)
#define S1_BASE 1024
#define S2_BASE 66560

// ----------------------- device scratch (no allocs allowed) ----------------
static __device__ float2 g_xh[B_N * T_N];                       // 2 MB
static __device__ float2 g_u1h[(size_t)B_N * N1 * T_N];         // 128 MB
static __device__ float  g_psi1p[N1 * T_N];                     // 4 MB
static __device__ float  g_psi2p[N2 * T_N];                     // 0.5 MB
static __device__ float2 g_tw[T_N];                             // e^{-2pi i k/N}
static __device__ float  g_phit[W_PHI + 1];                     // time-domain phi

// ----------------------- helpers -------------------------------------------
__device__ __forceinline__ float2 cmul(float2 a, float2 b) {
    return make_float2(fmaf(a.x, b.x, -a.y * b.y),
                       fmaf(a.x, b.y,  a.y * b.x));
}

__device__ __forceinline__ int drev4(int p) {
    int r = 0;
#pragma unroll
    for (int i = 0; i < 7; i++) { r = (r << 2) | (p & 3); p >>= 2; }
    return r;
}

// Forward radix-4 DIF, in-place in shared, natural in -> digit-reversed out.
// Unnormalized DFT with e^{-2pi i nk/N}.
__device__ void fft_dif(float2* s) {
    const int tid = threadIdx.x, nth = blockDim.x;
    __syncthreads();
    for (int L = T_N / 4; L >= 1; L >>= 2) {
        const int twst = (T_N / 4) / L;
        for (int i = tid; i < T_N / 4; i += nth) {
            const int j  = i & (L - 1);
            const int i0 = ((i - j) << 2) + j;
            float2 a = s[i0], b = s[i0 + L], c = s[i0 + 2 * L], d = s[i0 + 3 * L];
            float2 t0 = make_float2(a.x + c.x, a.y + c.y);
            float2 t1 = make_float2(a.x - c.x, a.y - c.y);
            float2 t2 = make_float2(b.x + d.x, b.y + d.y);
            float2 t3 = make_float2(b.x - d.x, b.y - d.y);
            float2 y0 = make_float2(t0.x + t2.x, t0.y + t2.y);
            float2 y2 = make_float2(t0.x - t2.x, t0.y - t2.y);
            float2 y1 = make_float2(t1.x + t3.y, t1.y - t3.x);   // t1 - i t3
            float2 y3 = make_float2(t1.x - t3.y, t1.y + t3.x);   // t1 + i t3
            float2 w1 = g_tw[j * twst];
            float2 w2 = cmul(w1, w1);
            float2 w3 = cmul(w2, w1);
            s[i0]         = y0;
            s[i0 + L]     = cmul(y1, w1);
            s[i0 + 2 * L] = cmul(y2, w2);
            s[i0 + 3 * L] = cmul(y3, w3);
        }
        __syncthreads();
    }
}

// Inverse radix-4 DIT, in-place, digit-reversed in -> natural out.
// Exact inverse of fft_dif times N (scale folded into filters).
__device__ void fft_dit_inv(float2* s) {
    const int tid = threadIdx.x, nth = blockDim.x;
    __syncthreads();
    for (int L = 1; L <= T_N / 4; L <<= 2) {
        const int twst = (T_N / 4) / L;
        for (int i = tid; i < T_N / 4; i += nth) {
            const int j  = i & (L - 1);
            const int i0 = ((i - j) << 2) + j;
            float2 y0 = s[i0], y1 = s[i0 + L], y2 = s[i0 + 2 * L], y3 = s[i0 + 3 * L];
            float2 w1 = g_tw[j * twst]; w1.y = -w1.y;            // conj
            float2 w2 = cmul(w1, w1);
            float2 w3 = cmul(w2, w1);
            float2 u1 = cmul(y1, w1);
            float2 u2 = cmul(y2, w2);
            float2 u3 = cmul(y3, w3);
            float2 s0 = make_float2(y0.x + u2.x, y0.y + u2.y);
            float2 s1 = make_float2(y0.x - u2.x, y0.y - u2.y);
            float2 s2 = make_float2(u1.x + u3.x, u1.y + u3.y);
            float2 s3 = make_float2(u1.x - u3.x, u1.y - u3.y);
            s[i0]         = make_float2(s0.x + s2.x, s0.y + s2.y);
            s[i0 + L]     = make_float2(s1.x - s3.y, s1.y + s3.x); // s1 + i s3
            s[i0 + 2 * L] = make_float2(s0.x - s2.x, s0.y - s2.y);
            s[i0 + 3 * L] = make_float2(s1.x + s3.y, s1.y - s3.x); // s1 - i s3
        }
        __syncthreads();
    }
}

// Time-domain lowpass (circular conv with g_phit) + downsample by 256.
// Reads .x of the shared complex array. One warp per 2 outputs.
__device__ void lowpass64(const float2* __restrict__ s, float* __restrict__ outp) {
    const int lane = threadIdx.x & 31;
    const int warp = threadIdx.x >> 5;
    const int nw   = blockDim.x >> 5;
    for (int m = warp; m < M_OUT; m += nw) {
        const int t0 = m << 8;
        float acc = 0.f;
        for (int dd = lane; dd < 2 * W_PHI + 1; dd += 32) {
            const int d   = dd - W_PHI;
            const int ad  = d < 0 ? -d : d;
            const int idx = (t0 - d + T_N) & (T_N - 1);
            acc = fmaf(s[idx].x, g_phit[ad], acc);
        }
#pragma unroll
        for (int off = 16; off; off >>= 1)
            acc += __shfl_down_sync(0xffffffffu, acc, off);
        if (lane == 0) outp[m] = acc;
    }
}

// ----------------------- init kernels ---------------------------------------
__global__ void k_init(const float* __restrict__ psi1,
                       const float* __restrict__ psi2) {
    const float invN = 1.0f / (float)T_N;
    const int total = N1 * T_N;
    for (int i = blockIdx.x * blockDim.x + threadIdx.x; i < total;
         i += gridDim.x * blockDim.x) {
        const int p = i & (T_N - 1);
        const int j = i >> 14;
        const int r = drev4(p);
        g_psi1p[i] = psi1[(j << 14) + r] * invN;
        if (j < N2) g_psi2p[i] = psi2[(j << 14) + r] * invN;
        if (j == 0) {
            float sn, cn;
            sincospif(-2.0f * (float)p / (float)T_N, &sn, &cn);
            g_tw[p] = make_float2(cn, sn);                 // e^{-2pi i p/N}
        }
    }
}

// phi_time[n] = (1/T) * sum_k phi_hat[k] * cos(2 pi k n / T), exact via g_tw.
__global__ void k_phit(const float* __restrict__ phi) {
    __shared__ float red[256];
    const int n = blockIdx.x;   // 0..W_PHI
    float acc = 0.f;
    for (int k = threadIdx.x; k < T_N; k += blockDim.x)
        acc = fmaf(phi[k], g_tw[(k * n) & (T_N - 1)].x, acc);
    red[threadIdx.x] = acc;
    __syncthreads();
    for (int off = 128; off; off >>= 1) {
        if (threadIdx.x < off) red[threadIdx.x] += red[threadIdx.x + off];
        __syncthreads();
    }
    if (threadIdx.x == 0) g_phit[n] = red[0] * (1.0f / (float)T_N);
}

// ----------------------- main kernels ---------------------------------------
// x FFT + S0.  One CTA per batch row.
__global__ void __launch_bounds__(1024, 1)
k_xfft(const float* __restrict__ x, float* __restrict__ out) {
    extern __shared__ float2 s[];
    const int b = blockIdx.x;
    const float* xb = x + b * T_N;
    for (int i = threadIdx.x; i < T_N; i += blockDim.x)
        s[i] = make_float2(xb[i], 0.f);
    __syncthreads();
    lowpass64(s, out + b * M_OUT);          // S0
    fft_dif(s);                              // (leading sync protects conv)
    float2* dst = g_xh + b * T_N;
    for (int i = threadIdx.x; i < T_N; i += blockDim.x)
        dst[i] = s[i];
}

// Order 1: IFFT(xh*psi1) -> |.| -> S1 conv -> FFT -> U1h.  1024 CTAs.
__global__ void __launch_bounds__(1024, 1)
k_order1(float* __restrict__ out) {
    extern __shared__ float2 s[];
    const int j1 = blockIdx.x;   // 0..63
    const int b  = blockIdx.y;   // 0..15
    const float2* xh  = g_xh + b * T_N;
    const float*  psi = g_psi1p + j1 * T_N;
    for (int i = threadIdx.x; i < T_N; i += blockDim.x) {
        float2 v = xh[i];
        float  p = psi[i];
        s[i] = make_float2(v.x * p, v.y * p);
    }
    fft_dit_inv(s);
    for (int i = threadIdx.x; i < T_N; i += blockDim.x) {
        float2 v = s[i];
        s[i] = make_float2(sqrtf(fmaf(v.x, v.x, v.y * v.y)), 0.f);
    }
    __syncthreads();
    lowpass64(s, out + S1_BASE + (b * N1 + j1) * M_OUT);   // S1
    fft_dif(s);
    float2* dst = g_u1h + (size_t)(b * N1 + j1) * T_N;
    for (int i = threadIdx.x; i < T_N; i += blockDim.x)
        dst[i] = s[i];
}

// Order 2: IFFT(U1h*psi2) -> |.| -> S2 conv.  3584 CTAs.
__global__ void __launch_bounds__(1024, 1)
k_order2(const int* __restrict__ pj1, const int* __restrict__ pj2,
         float* __restrict__ out) {
    extern __shared__ float2 s[];
    const int idx = blockIdx.x;          // 0..3583
    const int b   = idx / P_N;
    const int p   = idx - b * P_N;
    const int j1  = pj1[p];
    const int j2  = pj2[p];
    const float2* uh  = g_u1h + (size_t)(b * N1 + j1) * T_N;
    const float*  psi = g_psi2p + j2 * T_N;
    for (int i = threadIdx.x; i < T_N; i += blockDim.x) {
        float2 v = uh[i];
        float  w = psi[i];
        s[i] = make_float2(v.x * w, v.y * w);
    }
    fft_dit_inv(s);
    for (int i = threadIdx.x; i < T_N; i += blockDim.x) {
        float2 v = s[i];
        s[i].x = sqrtf(fmaf(v.x, v.x, v.y * v.y));
    }
    __syncthreads();
    lowpass64(s, out + S2_BASE + (b * P_N + p) * M_OUT);   // S2
}

// ----------------------- launch --------------------------------------------
extern "C" void kernel_launch(void* const* d_in, const int* in_sizes, int n_in,
                              void* d_out, int out_size) {
    (void)in_sizes; (void)n_in; (void)out_size;
    const float* x    = (const float*)d_in[0];
    const float* psi1 = (const float*)d_in[1];
    const float* psi2 = (const float*)d_in[2];
    const float* phi  = (const float*)d_in[3];
    const int*   pj1  = (const int*)d_in[4];
    const int*   pj2  = (const int*)d_in[5];
    float* out = (float*)d_out;

    cudaFuncSetAttribute(k_xfft,   cudaFuncAttributeMaxDynamicSharedMemorySize, SMEM_BYTES);
    cudaFuncSetAttribute(k_order1, cudaFuncAttributeMaxDynamicSharedMemorySize, SMEM_BYTES);
    cudaFuncSetAttribute(k_order2, cudaFuncAttributeMaxDynamicSharedMemorySize, SMEM_BYTES);

    k_init<<<512, 256>>>(psi1, psi2);
    k_phit<<<W_PHI + 1, 256>>>(phi);
    k_xfft<<<B_N, 1024, SMEM_BYTES>>>(x, out);
    dim3 g1(N1, B_N);
    k_order1<<<g1, 1024, SMEM_BYTES>>>(out);
    k_order2<<<B_N * P_N, 1024, SMEM_BYTES>>>(pj1, pj2, out);
}

// round 4
// speedup vs baseline: 1.9719x; 1.9719x over previous
#include <cuda_runtime.h>
#include <math.h>

// ---------------------------------------------------------------------------
// Wavelet scattering, T=16384, B=16, n1=64, n2=8, P=224, stride 256.
//
// R4: register-based radix-16 FFT (4 shared passes instead of 7), SoA shared
// layout with bank-conflict-free padding, gmem loads/stores + filter multiply
// + modulus fused into the boundary FFT passes, phi window 768 -> 512 taps.
// ---------------------------------------------------------------------------

#define T_N    16384
#define B_N    16
#define N1     64
#define N2     8
#define P_N    224
#define M_OUT  64
#define W_PHI  512
#define NPAD   (T_N + 1024)           // padded float array length
#define SMEM_BYTES ((2 * NPAD + W_PHI + 4) * (int)sizeof(float))

#define S1_BASE 1024
#define S2_BASE 66560

// ----------------------- device scratch ------------------------------------
static __device__ float2 g_xh[B_N * T_N];                     // 2 MB  (permuted)
static __device__ float2 g_u1h[(size_t)B_N * N1 * T_N];       // 128 MB (permuted)
static __device__ float  g_psi1p[N1 * T_N];                   // permuted, /N
static __device__ float  g_psi2p[N2 * T_N];
static __device__ float2 g_tw[T_N];                           // e^{-2pi i k/N}
static __device__ float  g_phit[W_PHI + 1];

// ----------------------- helpers -------------------------------------------
__device__ __forceinline__ int adr(int i) { return i + ((i >> 6) << 2); }

__device__ __forceinline__ float2 cmul(float2 a, float2 b) {
    return make_float2(fmaf(a.x, b.x, -a.y * b.y),
                       fmaf(a.x, b.y,  a.y * b.x));
}
__device__ __forceinline__ float2 cj(float2 a) { return make_float2(a.x, -a.y); }

// z * (c - i s)   (forward twiddle)
__device__ __forceinline__ float2 twf(float2 z, float c, float s) {
    return make_float2(fmaf(z.x, c,  z.y * s), fmaf(z.y, c, -z.x * s));
}
// z * (c + i s)   (inverse twiddle)
__device__ __forceinline__ float2 twi(float2 z, float c, float s) {
    return make_float2(fmaf(z.x, c, -z.y * s), fmaf(z.y, c,  z.x * s));
}

// forward radix-4 butterfly (omega = -i); outputs (y0,y1,y2,y3) in (A,B,C,D)
__device__ __forceinline__ void r4f(float2& A, float2& B, float2& C, float2& D) {
    float t0x = A.x + C.x, t0y = A.y + C.y, t1x = A.x - C.x, t1y = A.y - C.y;
    float t2x = B.x + D.x, t2y = B.y + D.y, t3x = B.x - D.x, t3y = B.y - D.y;
    A.x = t0x + t2x; A.y = t0y + t2y;  C.x = t0x - t2x; C.y = t0y - t2y;
    B.x = t1x + t3y; B.y = t1y - t3x;  D.x = t1x - t3y; D.y = t1y + t3x;
}
// inverse radix-4 butterfly (omega = +i)
__device__ __forceinline__ void r4i(float2& A, float2& B, float2& C, float2& D) {
    float t0x = A.x + C.x, t0y = A.y + C.y, t1x = A.x - C.x, t1y = A.y - C.y;
    float t2x = B.x + D.x, t2y = B.y + D.y, t3x = B.x - D.x, t3y = B.y - D.y;
    A.x = t0x + t2x; A.y = t0y + t2y;  C.x = t0x - t2x; C.y = t0y - t2y;
    B.x = t1x - t3y; B.y = t1y + t3x;  D.x = t1x + t3y; D.y = t1y - t3x;
}

#define C16_1 0.9238795325112867f
#define S16_1 0.3826834323650898f
#define RSQ2  0.7071067811865476f

// 16-point DFT, natural input order, base-4-digit-reversed output:
// reg p holds X[(p>>2) + 4*(p&3)].
__device__ __forceinline__ void dft16f(float2 a[16]) {
    r4f(a[0], a[4], a[8], a[12]); r4f(a[1], a[5], a[9], a[13]);
    r4f(a[2], a[6], a[10], a[14]); r4f(a[3], a[7], a[11], a[15]);
    a[5]  = twf(a[5],  C16_1,  S16_1);
    a[9]  = twf(a[9],  RSQ2,   RSQ2);
    a[13] = twf(a[13], S16_1,  C16_1);
    a[6]  = twf(a[6],  RSQ2,   RSQ2);
    a[10] = make_float2(a[10].y, -a[10].x);            // * (-i)
    a[14] = twf(a[14], -RSQ2,   RSQ2);
    a[7]  = twf(a[7],  S16_1,  C16_1);
    a[11] = twf(a[11], -RSQ2,   RSQ2);
    a[15] = twf(a[15], -C16_1, -S16_1);
    r4f(a[0], a[1], a[2], a[3]);   r4f(a[4], a[5], a[6], a[7]);
    r4f(a[8], a[9], a[10], a[11]); r4f(a[12], a[13], a[14], a[15]);
}
__device__ __forceinline__ void dft16i(float2 a[16]) {
    r4i(a[0], a[4], a[8], a[12]); r4i(a[1], a[5], a[9], a[13]);
    r4i(a[2], a[6], a[10], a[14]); r4i(a[3], a[7], a[11], a[15]);
    a[5]  = twi(a[5],  C16_1,  S16_1);
    a[9]  = twi(a[9],  RSQ2,   RSQ2);
    a[13] = twi(a[13], S16_1,  C16_1);
    a[6]  = twi(a[6],  RSQ2,   RSQ2);
    a[10] = make_float2(-a[10].y, a[10].x);            // * (+i)
    a[14] = twi(a[14], -RSQ2,   RSQ2);
    a[7]  = twi(a[7],  S16_1,  C16_1);
    a[11] = twi(a[11], -RSQ2,   RSQ2);
    a[15] = twi(a[15], -C16_1, -S16_1);
    r4i(a[0], a[1], a[2], a[3]);   r4i(a[4], a[5], a[6], a[7]);
    r4i(a[8], a[9], a[10], a[11]); r4i(a[12], a[13], a[14], a[15]);
}

// Forward radix-16 stage on shared (in-place per thread):
// reads natural offsets m, stores y_r * w1^r at offset r (reg p -> offset krev(p)).
__device__ __forceinline__ void bf16_fwd(float* __restrict__ re, float* __restrict__ im,
                                         int bp, int stride, float2 w1) {
    float2 a[16];
#pragma unroll
    for (int m = 0; m < 16; m++) {
        int A_ = adr(bp + stride * m);
        a[m] = make_float2(re[A_], im[A_]);
    }
    dft16f(a);
    { int A_ = adr(bp); re[A_] = a[0].x; im[A_] = a[0].y; }
    float2 cur = w1;
#pragma unroll
    for (int r = 1; r < 16; r++) {
        int p = ((r & 3) << 2) | (r >> 2);
        float2 v = cmul(a[p], cur);
        int A_ = adr(bp + stride * r);
        re[A_] = v.x; im[A_] = v.y;
        if (r < 15) cur = cmul(cur, w1);
    }
}

// Inverse radix-16 stage: reads offset r, un-twiddles by w1c^r (w1c = conj),
// inverse DFT16, stores X[m] at offset m. ABS: store |X| into re, 0 into im.
template<bool ABS>
__device__ __forceinline__ void bf16_inv(float* __restrict__ re, float* __restrict__ im,
                                         int bp, int stride, float2 w1c) {
    float2 a[16];
#pragma unroll
    for (int r = 0; r < 16; r++) {
        int A_ = adr(bp + stride * r);
        a[r] = make_float2(re[A_], im[A_]);
    }
    float2 cur = w1c;
#pragma unroll
    for (int r = 1; r < 16; r++) {
        a[r] = cmul(a[r], cur);
        if (r < 15) cur = cmul(cur, w1c);
    }
    dft16i(a);
#pragma unroll
    for (int m = 0; m < 16; m++) {
        int p = ((m & 3) << 2) | (m >> 2);
        int A_ = adr(bp + stride * m);
        if (ABS) {
            re[A_] = sqrtf(fmaf(a[p].x, a[p].x, a[p].y * a[p].y));
            im[A_] = 0.f;
        } else {
            re[A_] = a[p].x; im[A_] = a[p].y;
        }
    }
}

// Final forward radix-4 stage: shared -> gmem (permuted order), no twiddles.
__device__ __forceinline__ void pass4_fwd(const float* __restrict__ re,
                                          const float* __restrict__ im,
                                          int t, float2* __restrict__ dst) {
#pragma unroll
    for (int h = 0; h < 8; h++) {
        int i0 = 4 * (t + 512 * h);
        int A0 = adr(i0);
        float4 rr = *(const float4*)(re + A0);
        float4 ii = *(const float4*)(im + A0);
        float2 A = make_float2(rr.x, ii.x), B = make_float2(rr.y, ii.y);
        float2 C = make_float2(rr.z, ii.z), D = make_float2(rr.w, ii.w);
        r4f(A, B, C, D);
        float4* dp = (float4*)(dst + i0);
        dp[0] = make_float4(A.x, A.y, B.x, B.y);
        dp[1] = make_float4(C.x, C.y, D.x, D.y);
    }
}

// Entry inverse radix-4 stage: gmem * psi -> shared, no twiddles.
__device__ __forceinline__ void pass4_inv(float* __restrict__ re, float* __restrict__ im,
                                          int t, const float2* __restrict__ src,
                                          const float* __restrict__ psi) {
#pragma unroll
    for (int h = 0; h < 8; h++) {
        int i0 = 4 * (t + 512 * h);
        const float4* sp = (const float4*)(src + i0);
        float4 v1 = sp[0], v2 = sp[1];
        float4 p4 = *(const float4*)(psi + i0);
        float2 A = make_float2(v1.x * p4.x, v1.y * p4.x);
        float2 B = make_float2(v1.z * p4.y, v1.w * p4.y);
        float2 C = make_float2(v2.x * p4.z, v2.y * p4.z);
        float2 D = make_float2(v2.z * p4.w, v2.w * p4.w);
        r4i(A, B, C, D);
        int A0 = adr(i0);
        *(float4*)(re + A0) = make_float4(A.x, B.x, C.x, D.x);
        *(float4*)(im + A0) = make_float4(A.y, B.y, C.y, D.y);
    }
}

// 3 inner forward passes (strides 1024, 64, 4) on shared.
__device__ __forceinline__ void fwd3(float* re, float* im, int t) {
#pragma unroll
    for (int q = 0; q < 2; q++) { int tt = t + 512 * q; bf16_fwd(re, im, tt, 1024, g_tw[tt]); }
    __syncthreads();
#pragma unroll
    for (int q = 0; q < 2; q++) {
        int tt = t + 512 * q;
        bf16_fwd(re, im, ((tt >> 6) << 10) + (tt & 63), 64, g_tw[(tt & 63) << 4]);
    }
    __syncthreads();
#pragma unroll
    for (int q = 0; q < 2; q++) {
        int tt = t + 512 * q;
        bf16_fwd(re, im, ((tt >> 2) << 6) + (tt & 3), 4, g_tw[(tt & 3) << 8]);
    }
    __syncthreads();
}

// 3 inner inverse passes (strides 4, 64, 1024); last one optionally takes |.|
template<bool ABS>
__device__ __forceinline__ void inv3(float* re, float* im, int t) {
#pragma unroll
    for (int q = 0; q < 2; q++) {
        int tt = t + 512 * q;
        bf16_inv<false>(re, im, ((tt >> 2) << 6) + (tt & 3), 4, cj(g_tw[(tt & 3) << 8]));
    }
    __syncthreads();
#pragma unroll
    for (int q = 0; q < 2; q++) {
        int tt = t + 512 * q;
        bf16_inv<false>(re, im, ((tt >> 6) << 10) + (tt & 63), 64, cj(g_tw[(tt & 63) << 4]));
    }
    __syncthreads();
#pragma unroll
    for (int q = 0; q < 2; q++) { int tt = t + 512 * q; bf16_inv<ABS>(re, im, tt, 1024, cj(g_tw[tt])); }
    __syncthreads();
}

// Time-domain lowpass + downsample by 256 (reads padded re array).
__device__ __forceinline__ void lowpass64(const float* __restrict__ re,
                                          const float* __restrict__ ph,
                                          float* __restrict__ outp) {
    const int lane = threadIdx.x & 31;
    const int warp = threadIdx.x >> 5;
    for (int m = warp; m < M_OUT; m += 16) {
        const int t0 = m << 8;
        float acc = 0.f;
        for (int dd = lane; dd <= 2 * W_PHI; dd += 32) {
            const int d   = dd - W_PHI;
            const int ad  = d < 0 ? -d : d;
            const int idx = (t0 - d + T_N) & (T_N - 1);
            acc = fmaf(re[adr(idx)], ph[ad], acc);
        }
#pragma unroll
        for (int off = 16; off; off >>= 1)
            acc += __shfl_down_sync(0xffffffffu, acc, off);
        if (lane == 0) outp[m] = acc;
    }
}

// ----------------------- init kernels ---------------------------------------
__device__ __forceinline__ int posrm(int k) {
    return ((k & 15) << 10) | (((k >> 4) & 15) << 6) | (((k >> 8) & 15) << 2) | (k >> 12);
}

__global__ void k_init(const float* __restrict__ psi1, const float* __restrict__ psi2) {
    const float invN = 1.0f / (float)T_N;
    const int total = N1 * T_N;
    for (int i = blockIdx.x * blockDim.x + threadIdx.x; i < total;
         i += gridDim.x * blockDim.x) {
        const int k = i & (T_N - 1);
        const int j = i >> 14;
        const int pos = posrm(k);
        g_psi1p[(j << 14) + pos] = psi1[i] * invN;
        if (j < N2) g_psi2p[(j << 14) + pos] = psi2[i] * invN;
        if (j == 0) {
            float sn, cn;
            sincospif(-2.0f * (float)k / (float)T_N, &sn, &cn);
            g_tw[k] = make_float2(cn, sn);
        }
    }
}

__global__ void k_phit(const float* __restrict__ phi) {
    __shared__ float red[256];
    const int n = blockIdx.x;   // 0..W_PHI
    float acc = 0.f;
    for (int k = threadIdx.x; k < T_N; k += blockDim.x)
        acc = fmaf(phi[k], g_tw[(k * n) & (T_N - 1)].x, acc);
    red[threadIdx.x] = acc;
    __syncthreads();
    for (int off = 128; off; off >>= 1) {
        if (threadIdx.x < off) red[threadIdx.x] += red[threadIdx.x + off];
        __syncthreads();
    }
    if (threadIdx.x == 0) g_phit[n] = red[0] * (1.0f / (float)T_N);
}

// ----------------------- main kernels ---------------------------------------
__global__ void __launch_bounds__(512)
k_xfft(const float* __restrict__ x, float* __restrict__ out) {
    extern __shared__ float sm[];
    float* re = sm; float* im = sm + NPAD; float* ph = sm + 2 * NPAD;
    const int b = blockIdx.x, t = threadIdx.x;
    for (int i = t; i <= W_PHI; i += 512) ph[i] = g_phit[i];
    const float* xb = x + b * T_N;
    for (int i = t; i < T_N; i += 512) { int A_ = adr(i); re[A_] = xb[i]; im[A_] = 0.f; }
    __syncthreads();
    lowpass64(re, ph, out + b * M_OUT);                 // S0
    __syncthreads();
    fwd3(re, im, t);
    pass4_fwd(re, im, t, g_xh + b * T_N);
}

__global__ void __launch_bounds__(512)
k_order1(float* __restrict__ out) {
    extern __shared__ float sm[];
    float* re = sm; float* im = sm + NPAD; float* ph = sm + 2 * NPAD;
    const int j1 = blockIdx.x, b = blockIdx.y, t = threadIdx.x;
    for (int i = t; i <= W_PHI; i += 512) ph[i] = g_phit[i];
    pass4_inv(re, im, t, g_xh + b * T_N, g_psi1p + j1 * T_N);
    __syncthreads();
    inv3<true>(re, im, t);                               // |ifft|, im=0
    lowpass64(re, ph, out + S1_BASE + (b * N1 + j1) * M_OUT);   // S1
    __syncthreads();
    fwd3(re, im, t);
    pass4_fwd(re, im, t, g_u1h + (size_t)(b * N1 + j1) * T_N);
}

__global__ void __launch_bounds__(512)
k_order2(const int* __restrict__ pj1, const int* __restrict__ pj2,
         float* __restrict__ out) {
    extern __shared__ float sm[];
    float* re = sm; float* im = sm + NPAD; float* ph = sm + 2 * NPAD;
    const int idx = blockIdx.x, t = threadIdx.x;
    const int b = idx / P_N;
    const int p = idx - b * P_N;
    const int j1 = pj1[p], j2 = pj2[p];
    for (int i = t; i <= W_PHI; i += 512) ph[i] = g_phit[i];
    pass4_inv(re, im, t, g_u1h + (size_t)(b * N1 + j1) * T_N, g_psi2p + j2 * T_N);
    __syncthreads();
    inv3<true>(re, im, t);
    lowpass64(re, ph, out + S2_BASE + (b * P_N + p) * M_OUT);   // S2
}

// ----------------------- launch --------------------------------------------
extern "C" void kernel_launch(void* const* d_in, const int* in_sizes, int n_in,
                              void* d_out, int out_size) {
    (void)in_sizes; (void)n_in; (void)out_size;
    const float* x    = (const float*)d_in[0];
    const float* psi1 = (const float*)d_in[1];
    const float* psi2 = (const float*)d_in[2];
    const float* phi  = (const float*)d_in[3];
    const int*   pj1  = (const int*)d_in[4];
    const int*   pj2  = (const int*)d_in[5];
    float* out = (float*)d_out;

    cudaFuncSetAttribute(k_xfft,   cudaFuncAttributeMaxDynamicSharedMemorySize, SMEM_BYTES);
    cudaFuncSetAttribute(k_order1, cudaFuncAttributeMaxDynamicSharedMemorySize, SMEM_BYTES);
    cudaFuncSetAttribute(k_order2, cudaFuncAttributeMaxDynamicSharedMemorySize, SMEM_BYTES);

    k_init<<<256, 256>>>(psi1, psi2);
    k_phit<<<W_PHI + 1, 256>>>(phi);
    k_xfft<<<B_N, 512, SMEM_BYTES>>>(x, out);
    dim3 g1(N1, B_N);
    k_order1<<<g1, 512, SMEM_BYTES>>>(out);
    k_order2<<<B_N * P_N, 512, SMEM_BYTES>>>(pj1, pj2, out);
}

// round 5
// speedup vs baseline: 2.0150x; 1.0219x over previous
#include <cuda_runtime.h>
#include <math.h>

// ---------------------------------------------------------------------------
// Wavelet scattering, T=16384, B=16, n1=64, n2=8, P=224, stride 256.
//
// R5: 1024 threads/CTA (32 warps, 1 radix-16 butterfly per thread per pass)
// to cover LDS/issue latency; real-input forward-FFT first pass and no
// zero-imag stores after the modulus. Same 4-pass radix-16 structure,
// SoA + padding (conflict-free), fused gmem boundaries, time-domain phi.
// ---------------------------------------------------------------------------

#define T_N    16384
#define B_N    16
#define N1     64
#define N2     8
#define P_N    224
#define M_OUT  64
#define W_PHI  512
#define NPAD   (T_N + 1024)           // padded float array length
#define SMEM_BYTES ((2 * NPAD + W_PHI + 4) * (int)sizeof(float))

#define S1_BASE 1024
#define S2_BASE 66560

// ----------------------- device scratch ------------------------------------
static __device__ float2 g_xh[B_N * T_N];                     // 2 MB  (permuted)
static __device__ float2 g_u1h[(size_t)B_N * N1 * T_N];       // 128 MB (permuted)
static __device__ float  g_psi1p[N1 * T_N];                   // permuted, /N
static __device__ float  g_psi2p[N2 * T_N];
static __device__ float2 g_tw[T_N];                           // e^{-2pi i k/N}
static __device__ float  g_phit[W_PHI + 1];

// ----------------------- helpers -------------------------------------------
__device__ __forceinline__ int adr(int i) { return i + ((i >> 6) << 2); }

__device__ __forceinline__ float2 cmul(float2 a, float2 b) {
    return make_float2(fmaf(a.x, b.x, -a.y * b.y),
                       fmaf(a.x, b.y,  a.y * b.x));
}
__device__ __forceinline__ float2 cj(float2 a) { return make_float2(a.x, -a.y); }

__device__ __forceinline__ float2 twf(float2 z, float c, float s) {
    return make_float2(fmaf(z.x, c,  z.y * s), fmaf(z.y, c, -z.x * s));
}
__device__ __forceinline__ float2 twi(float2 z, float c, float s) {
    return make_float2(fmaf(z.x, c, -z.y * s), fmaf(z.y, c,  z.x * s));
}

__device__ __forceinline__ void r4f(float2& A, float2& B, float2& C, float2& D) {
    float t0x = A.x + C.x, t0y = A.y + C.y, t1x = A.x - C.x, t1y = A.y - C.y;
    float t2x = B.x + D.x, t2y = B.y + D.y, t3x = B.x - D.x, t3y = B.y - D.y;
    A.x = t0x + t2x; A.y = t0y + t2y;  C.x = t0x - t2x; C.y = t0y - t2y;
    B.x = t1x + t3y; B.y = t1y - t3x;  D.x = t1x - t3y; D.y = t1y + t3x;
}
__device__ __forceinline__ void r4i(float2& A, float2& B, float2& C, float2& D) {
    float t0x = A.x + C.x, t0y = A.y + C.y, t1x = A.x - C.x, t1y = A.y - C.y;
    float t2x = B.x + D.x, t2y = B.y + D.y, t3x = B.x - D.x, t3y = B.y - D.y;
    A.x = t0x + t2x; A.y = t0y + t2y;  C.x = t0x - t2x; C.y = t0y - t2y;
    B.x = t1x - t3y; B.y = t1y + t3x;  D.x = t1x + t3y; D.y = t1y - t3x;
}

#define C16_1 0.9238795325112867f
#define S16_1 0.3826834323650898f
#define RSQ2  0.7071067811865476f

// 16-point DFT, natural input, base-4-digit-reversed register output.
__device__ __forceinline__ void dft16f(float2 a[16]) {
    r4f(a[0], a[4], a[8], a[12]); r4f(a[1], a[5], a[9], a[13]);
    r4f(a[2], a[6], a[10], a[14]); r4f(a[3], a[7], a[11], a[15]);
    a[5]  = twf(a[5],  C16_1,  S16_1);
    a[9]  = twf(a[9],  RSQ2,   RSQ2);
    a[13] = twf(a[13], S16_1,  C16_1);
    a[6]  = twf(a[6],  RSQ2,   RSQ2);
    a[10] = make_float2(a[10].y, -a[10].x);
    a[14] = twf(a[14], -RSQ2,   RSQ2);
    a[7]  = twf(a[7],  S16_1,  C16_1);
    a[11] = twf(a[11], -RSQ2,   RSQ2);
    a[15] = twf(a[15], -C16_1, -S16_1);
    r4f(a[0], a[1], a[2], a[3]);   r4f(a[4], a[5], a[6], a[7]);
    r4f(a[8], a[9], a[10], a[11]); r4f(a[12], a[13], a[14], a[15]);
}
__device__ __forceinline__ void dft16i(float2 a[16]) {
    r4i(a[0], a[4], a[8], a[12]); r4i(a[1], a[5], a[9], a[13]);
    r4i(a[2], a[6], a[10], a[14]); r4i(a[3], a[7], a[11], a[15]);
    a[5]  = twi(a[5],  C16_1,  S16_1);
    a[9]  = twi(a[9],  RSQ2,   RSQ2);
    a[13] = twi(a[13], S16_1,  C16_1);
    a[6]  = twi(a[6],  RSQ2,   RSQ2);
    a[10] = make_float2(-a[10].y, a[10].x);
    a[14] = twi(a[14], -RSQ2,   RSQ2);
    a[7]  = twi(a[7],  S16_1,  C16_1);
    a[11] = twi(a[11], -RSQ2,   RSQ2);
    a[15] = twi(a[15], -C16_1, -S16_1);
    r4i(a[0], a[1], a[2], a[3]);   r4i(a[4], a[5], a[6], a[7]);
    r4i(a[8], a[9], a[10], a[11]); r4i(a[12], a[13], a[14], a[15]);
}

// Forward radix-16 stage (complex input).
__device__ __forceinline__ void bf16_fwd(float* __restrict__ re, float* __restrict__ im,
                                         int bp, int stride, float2 w1) {
    float2 a[16];
#pragma unroll
    for (int m = 0; m < 16; m++) {
        int A_ = adr(bp + stride * m);
        a[m] = make_float2(re[A_], im[A_]);
    }
    dft16f(a);
    { int A_ = adr(bp); re[A_] = a[0].x; im[A_] = a[0].y; }
    float2 cur = w1;
#pragma unroll
    for (int r = 1; r < 16; r++) {
        int p = ((r & 3) << 2) | (r >> 2);
        float2 v = cmul(a[p], cur);
        int A_ = adr(bp + stride * r);
        re[A_] = v.x; im[A_] = v.y;
        if (r < 15) cur = cmul(cur, w1);
    }
}

// Forward radix-16 stage, REAL input (im assumed zero, not read).
__device__ __forceinline__ void bf16_fwd_real(float* __restrict__ re, float* __restrict__ im,
                                              int bp, int stride, float2 w1) {
    float2 a[16];
#pragma unroll
    for (int m = 0; m < 16; m++) {
        int A_ = adr(bp + stride * m);
        a[m] = make_float2(re[A_], 0.f);
    }
    dft16f(a);
    { int A_ = adr(bp); re[A_] = a[0].x; im[A_] = a[0].y; }
    float2 cur = w1;
#pragma unroll
    for (int r = 1; r < 16; r++) {
        int p = ((r & 3) << 2) | (r >> 2);
        float2 v = cmul(a[p], cur);
        int A_ = adr(bp + stride * r);
        re[A_] = v.x; im[A_] = v.y;
        if (r < 15) cur = cmul(cur, w1);
    }
}

// Inverse radix-16 stage. ABS: store |X| into re only (im left stale/unused).
template<bool ABS>
__device__ __forceinline__ void bf16_inv(float* __restrict__ re, float* __restrict__ im,
                                         int bp, int stride, float2 w1c) {
    float2 a[16];
#pragma unroll
    for (int r = 0; r < 16; r++) {
        int A_ = adr(bp + stride * r);
        a[r] = make_float2(re[A_], im[A_]);
    }
    float2 cur = w1c;
#pragma unroll
    for (int r = 1; r < 16; r++) {
        a[r] = cmul(a[r], cur);
        if (r < 15) cur = cmul(cur, w1c);
    }
    dft16i(a);
#pragma unroll
    for (int m = 0; m < 16; m++) {
        int p = ((m & 3) << 2) | (m >> 2);
        int A_ = adr(bp + stride * m);
        if (ABS) {
            re[A_] = sqrtf(fmaf(a[p].x, a[p].x, a[p].y * a[p].y));
        } else {
            re[A_] = a[p].x; im[A_] = a[p].y;
        }
    }
}

// Final forward radix-4 stage: shared -> gmem (permuted order), no twiddles.
__device__ __forceinline__ void pass4_fwd(const float* __restrict__ re,
                                          const float* __restrict__ im,
                                          int t, float2* __restrict__ dst) {
#pragma unroll
    for (int h = 0; h < 4; h++) {
        int i0 = 4 * (t + 1024 * h);
        int A0 = adr(i0);
        float4 rr = *(const float4*)(re + A0);
        float4 ii = *(const float4*)(im + A0);
        float2 A = make_float2(rr.x, ii.x), B = make_float2(rr.y, ii.y);
        float2 C = make_float2(rr.z, ii.z), D = make_float2(rr.w, ii.w);
        r4f(A, B, C, D);
        float4* dp = (float4*)(dst + i0);
        dp[0] = make_float4(A.x, A.y, B.x, B.y);
        dp[1] = make_float4(C.x, C.y, D.x, D.y);
    }
}

// Entry inverse radix-4 stage: gmem * psi -> shared, no twiddles.
__device__ __forceinline__ void pass4_inv(float* __restrict__ re, float* __restrict__ im,
                                          int t, const float2* __restrict__ src,
                                          const float* __restrict__ psi) {
#pragma unroll
    for (int h = 0; h < 4; h++) {
        int i0 = 4 * (t + 1024 * h);
        const float4* sp = (const float4*)(src + i0);
        float4 v1 = sp[0], v2 = sp[1];
        float4 p4 = *(const float4*)(psi + i0);
        float2 A = make_float2(v1.x * p4.x, v1.y * p4.x);
        float2 B = make_float2(v1.z * p4.y, v1.w * p4.y);
        float2 C = make_float2(v2.x * p4.z, v2.y * p4.z);
        float2 D = make_float2(v2.z * p4.w, v2.w * p4.w);
        r4i(A, B, C, D);
        int A0 = adr(i0);
        *(float4*)(re + A0) = make_float4(A.x, B.x, C.x, D.x);
        *(float4*)(im + A0) = make_float4(A.y, B.y, C.y, D.y);
    }
}

// 3 inner forward passes (strides 1024, 64, 4). REAL_IN: first pass reads re only.
template<bool REAL_IN>
__device__ __forceinline__ void fwd3(float* re, float* im, int t) {
    if (REAL_IN) bf16_fwd_real(re, im, t, 1024, g_tw[t]);
    else         bf16_fwd     (re, im, t, 1024, g_tw[t]);
    __syncthreads();
    bf16_fwd(re, im, ((t >> 6) << 10) + (t & 63), 64, g_tw[(t & 63) << 4]);
    __syncthreads();
    bf16_fwd(re, im, ((t >> 2) << 6) + (t & 3), 4, g_tw[(t & 3) << 8]);
    __syncthreads();
}

// 3 inner inverse passes (strides 4, 64, 1024); last optionally takes |.|
template<bool ABS>
__device__ __forceinline__ void inv3(float* re, float* im, int t) {
    bf16_inv<false>(re, im, ((t >> 2) << 6) + (t & 3), 4, cj(g_tw[(t & 3) << 8]));
    __syncthreads();
    bf16_inv<false>(re, im, ((t >> 6) << 10) + (t & 63), 64, cj(g_tw[(t & 63) << 4]));
    __syncthreads();
    bf16_inv<ABS>(re, im, t, 1024, cj(g_tw[t]));
    __syncthreads();
}

// Time-domain lowpass + downsample by 256 (reads padded re array).
__device__ __forceinline__ void lowpass64(const float* __restrict__ re,
                                          const float* __restrict__ ph,
                                          float* __restrict__ outp) {
    const int lane = threadIdx.x & 31;
    const int warp = threadIdx.x >> 5;
    for (int m = warp; m < M_OUT; m += 32) {
        const int t0 = m << 8;
        float acc = 0.f;
        for (int dd = lane; dd <= 2 * W_PHI; dd += 32) {
            const int d   = dd - W_PHI;
            const int ad  = d < 0 ? -d : d;
            const int idx = (t0 - d + T_N) & (T_N - 1);
            acc = fmaf(re[adr(idx)], ph[ad], acc);
        }
#pragma unroll
        for (int off = 16; off; off >>= 1)
            acc += __shfl_down_sync(0xffffffffu, acc, off);
        if (lane == 0) outp[m] = acc;
    }
}

// ----------------------- init kernels ---------------------------------------
__device__ __forceinline__ int posrm(int k) {
    return ((k & 15) << 10) | (((k >> 4) & 15) << 6) | (((k >> 8) & 15) << 2) | (k >> 12);
}

__global__ void k_init(const float* __restrict__ psi1, const float* __restrict__ psi2) {
    const float invN = 1.0f / (float)T_N;
    const int total = N1 * T_N;
    for (int i = blockIdx.x * blockDim.x + threadIdx.x; i < total;
         i += gridDim.x * blockDim.x) {
        const int k = i & (T_N - 1);
        const int j = i >> 14;
        const int pos = posrm(k);
        g_psi1p[(j << 14) + pos] = psi1[i] * invN;
        if (j < N2) g_psi2p[(j << 14) + pos] = psi2[i] * invN;
        if (j == 0) {
            float sn, cn;
            sincospif(-2.0f * (float)k / (float)T_N, &sn, &cn);
            g_tw[k] = make_float2(cn, sn);
        }
    }
}

__global__ void k_phit(const float* __restrict__ phi) {
    __shared__ float red[256];
    const int n = blockIdx.x;   // 0..W_PHI
    float acc = 0.f;
    for (int k = threadIdx.x; k < T_N; k += blockDim.x)
        acc = fmaf(phi[k], g_tw[(k * n) & (T_N - 1)].x, acc);
    red[threadIdx.x] = acc;
    __syncthreads();
    for (int off = 128; off; off >>= 1) {
        if (threadIdx.x < off) red[threadIdx.x] += red[threadIdx.x + off];
        __syncthreads();
    }
    if (threadIdx.x == 0) g_phit[n] = red[0] * (1.0f / (float)T_N);
}

// ----------------------- main kernels ---------------------------------------
__global__ void __launch_bounds__(1024, 1)
k_xfft(const float* __restrict__ x, float* __restrict__ out) {
    extern __shared__ float sm[];
    float* re = sm; float* im = sm + NPAD; float* ph = sm + 2 * NPAD;
    const int b = blockIdx.x, t = threadIdx.x;
    for (int i = t; i <= W_PHI; i += 1024) ph[i] = g_phit[i];
    const float* xb = x + b * T_N;
    for (int i = t; i < T_N; i += 1024) re[adr(i)] = xb[i];
    __syncthreads();
    lowpass64(re, ph, out + b * M_OUT);                 // S0
    __syncthreads();
    fwd3<true>(re, im, t);
    pass4_fwd(re, im, t, g_xh + b * T_N);
}

__global__ void __launch_bounds__(1024, 1)
k_order1(float* __restrict__ out) {
    extern __shared__ float sm[];
    float* re = sm; float* im = sm + NPAD; float* ph = sm + 2 * NPAD;
    const int j1 = blockIdx.x, b = blockIdx.y, t = threadIdx.x;
    for (int i = t; i <= W_PHI; i += 1024) ph[i] = g_phit[i];
    pass4_inv(re, im, t, g_xh + b * T_N, g_psi1p + j1 * T_N);
    __syncthreads();
    inv3<true>(re, im, t);                               // |ifft| -> re
    lowpass64(re, ph, out + S1_BASE + (b * N1 + j1) * M_OUT);   // S1
    __syncthreads();
    fwd3<true>(re, im, t);
    pass4_fwd(re, im, t, g_u1h + (size_t)(b * N1 + j1) * T_N);
}

__global__ void __launch_bounds__(1024, 1)
k_order2(const int* __restrict__ pj1, const int* __restrict__ pj2,
         float* __restrict__ out) {
    extern __shared__ float sm[];
    float* re = sm; float* im = sm + NPAD; float* ph = sm + 2 * NPAD;
    const int idx = blockIdx.x, t = threadIdx.x;
    const int b = idx / P_N;
    const int p = idx - b * P_N;
    const int j1 = pj1[p], j2 = pj2[p];
    for (int i = t; i <= W_PHI; i += 1024) ph[i] = g_phit[i];
    pass4_inv(re, im, t, g_u1h + (size_t)(b * N1 + j1) * T_N, g_psi2p + j2 * T_N);
    __syncthreads();
    inv3<true>(re, im, t);
    lowpass64(re, ph, out + S2_BASE + (b * P_N + p) * M_OUT);   // S2
}

// ----------------------- launch --------------------------------------------
extern "C" void kernel_launch(void* const* d_in, const int* in_sizes, int n_in,
                              void* d_out, int out_size) {
    (void)in_sizes; (void)n_in; (void)out_size;
    const float* x    = (const float*)d_in[0];
    const float* psi1 = (const float*)d_in[1];
    const float* psi2 = (const float*)d_in[2];
    const float* phi  = (const float*)d_in[3];
    const int*   pj1  = (const int*)d_in[4];
    const int*   pj2  = (const int*)d_in[5];
    float* out = (float*)d_out;

    cudaFuncSetAttribute(k_xfft,   cudaFuncAttributeMaxDynamicSharedMemorySize, SMEM_BYTES);
    cudaFuncSetAttribute(k_order1, cudaFuncAttributeMaxDynamicSharedMemorySize, SMEM_BYTES);
    cudaFuncSetAttribute(k_order2, cudaFuncAttributeMaxDynamicSharedMemorySize, SMEM_BYTES);

    k_init<<<256, 256>>>(psi1, psi2);
    k_phit<<<W_PHI + 1, 256>>>(phi);
    k_xfft<<<B_N, 1024, SMEM_BYTES>>>(x, out);
    dim3 g1(N1, B_N);
    k_order1<<<g1, 1024, SMEM_BYTES>>>(out);
    k_order2<<<B_N * P_N, 1024, SMEM_BYTES>>>(pj1, pj2, out);
}